// round 11
// baseline (speedup 1.0000x reference)
#include <cuda_runtime.h>
#include <cuda_bf16.h>
#include <cuda_fp16.h>
#include <cstdint>

// GNN_9869834846215: two-layer cached GCN.
//   g = h W (fp16)     -- persistent HMMA bf16x2-split GEMM (no dinv)
//   out[d] = dinv[d]*(Σ_{s∈N(d)} dinv[s]·g[s] + dinv[d]·g[d]) + b
// CSR build runs on a side stream, overlapped with the layer-1 GEMM.

#define NMAX 100000
#define EMAX 1700000
#define FD 128
#define SCAN_T 1024
#define SCAN_C 4096
#define SCAN_NBLK 25                      // ceil(100000/4096)
#define NSM 148

#define BSTRIDE 136                       // bf16 row stride (272B): ldmatrix conflict-free
#define T_SH (128 * BSTRIDE * 2)          // 34816 B (128-row bf16 tile: B images)
#define A_SH (64 * BSTRIDE * 2)           // 17408 B (64-row bf16 tile: A images)
#define GEMM_SMEM (2 * T_SH + 2 * A_SH)   // 104448 B -> 2 blocks/SM

// Scratch (__device__ globals per allocation-free rule)
__device__ float d_dinv[NMAX];
__device__ float d_bufA[(size_t)NMAX * FD];   // g (fp16, viewed as half*)
__device__ float d_bufB[(size_t)NMAX * FD];   // h (fp32)
__device__ int   d_degi[NMAX];
__device__ int   d_off[NMAX + 1];
__device__ int   d_cursor[NMAX];
__device__ int   d_csr[EMAX];
__device__ int   d_blocksums[32];
// W^T split into bf16 hi/lo, layout [n][k] with row stride BSTRIDE
__device__ __align__(16) unsigned short d_Whi[128 * BSTRIDE];
__device__ __align__(16) unsigned short d_Wlo[128 * BSTRIDE];

// ---------------------------------------------------------------------------
__device__ __forceinline__ uint32_t smem_u32(const void* p) {
    uint32_t a;
    asm("{ .reg .u64 t; cvta.to.shared.u64 t, %1; cvt.u32.u64 %0, t; }"
        : "=r"(a) : "l"(p));
    return a;
}

__device__ __forceinline__ void ldm_x4(uint32_t* r, uint32_t addr) {
    asm volatile("ldmatrix.sync.aligned.m8n8.x4.shared.b16 {%0,%1,%2,%3}, [%4];"
                 : "=r"(r[0]), "=r"(r[1]), "=r"(r[2]), "=r"(r[3]) : "r"(addr));
}

__device__ __forceinline__ void mma_bf16(float* c, const uint32_t* a,
                                         const uint32_t* b) {
    asm volatile(
        "mma.sync.aligned.m16n8k16.row.col.f32.bf16.bf16.f32 "
        "{%0,%1,%2,%3}, {%4,%5,%6,%7}, {%8,%9}, {%0,%1,%2,%3};"
        : "+f"(c[0]), "+f"(c[1]), "+f"(c[2]), "+f"(c[3])
        : "r"(a[0]), "r"(a[1]), "r"(a[2]), "r"(a[3]), "r"(b[0]), "r"(b[1]));
}

__device__ __forceinline__ unsigned short bfbits(__nv_bfloat16 h) {
    return __bfloat16_as_ushort(h);
}

// Block-local edge-dtype detection (int64 vs int32); node ids < 2^31 so
// int64 data has zero high words in the first 64 pairs.
__device__ __forceinline__ int detect64_local(const void* ei, int* s64) {
    if (threadIdx.x == 0) {
        const int2* p = (const int2*)ei;
        int is64 = 1;
        for (int j = 0; j < 64; ++j)
            if (p[j].y != 0) { is64 = 0; break; }
        *s64 = is64;
    }
    __syncthreads();
    return *s64;
}

// ---------------------------------------------------------------------------
// Split one W element into the hi/lo B images. B[n][k] = W[k][n].
__device__ __forceinline__ void w_split_elem(const float* W, int idx) {
    int nn = idx & 127, kk = idx >> 7;
    float v = W[kk * FD + nn];
    __nv_bfloat16 hi = __float2bfloat16_rn(v);
    __nv_bfloat16 lo = __float2bfloat16_rn(v - __bfloat162float(hi));
    d_Whi[nn * BSTRIDE + kk] = bfbits(hi);
    d_Wlo[nn * BSTRIDE + kk] = bfbits(lo);
}

__global__ void w_split(const float* __restrict__ W) {
    int idx = blockIdx.x * 256 + threadIdx.x;
    if (idx < 16384) w_split_elem(W, idx);
}

__global__ void deg_count(const void* __restrict__ ei, int E) {
    __shared__ int s64;
    int is64 = detect64_local(ei, &s64);
    int i = blockIdx.x * blockDim.x + threadIdx.x;
    if (i >= E) return;
    int d = is64 ? (int)((const long long*)ei)[(size_t)E + i]
                 : ((const int*)ei)[(size_t)E + i];
    atomicAdd(&d_degi[d], 1);
}

// Chunked exclusive degree scan; also computes dinv.
__global__ void __launch_bounds__(SCAN_T)
scan_partial(int n) {
    __shared__ int ssum[SCAN_T];
    const int tid  = threadIdx.x;
    const int base = blockIdx.x * SCAN_C + tid * 4;

    int v[4];
#pragma unroll
    for (int i = 0; i < 4; ++i) {
        v[i] = (base + i < n) ? d_degi[base + i] : 0;
        if (base + i < n) d_dinv[base + i] = rsqrtf((float)v[i] + 1.0f);
    }
    int tsum = v[0] + v[1] + v[2] + v[3];
    ssum[tid] = tsum;
    __syncthreads();
    for (int off = 1; off < SCAN_T; off <<= 1) {
        int t = (tid >= off) ? ssum[tid - off] : 0;
        __syncthreads();
        ssum[tid] += t;
        __syncthreads();
    }
    int texcl = ssum[tid] - tsum;
    if (tid == SCAN_T - 1) d_blocksums[blockIdx.x] = ssum[tid];

    int run = texcl;
#pragma unroll
    for (int i = 0; i < 4; ++i) {
        if (base + i < n) d_off[base + i] = run;
        run += v[i];
    }
}

__global__ void scan_blocksums(int nblk) {
    int tid = threadIdx.x;
    int v = (tid < nblk) ? d_blocksums[tid] : 0;
    int orig = v;
#pragma unroll
    for (int o = 1; o < 32; o <<= 1) {
        int t = __shfl_up_sync(0xFFFFFFFFu, v, o);
        if (tid >= o) v += t;
    }
    if (tid < nblk) d_blocksums[tid] = v - orig;
}

__global__ void scan_add(int n, int E) {
    int i = blockIdx.x * blockDim.x + threadIdx.x;
    if (i < n) {
        int v = d_off[i] + d_blocksums[i / SCAN_C];
        d_off[i] = v;
        d_cursor[i] = v;
    }
    if (i == 0) d_off[n] = E;
}

// scatter_csr + W2 split: scatter blocks [0,sblk), W2-split blocks [sblk,+64)
__global__ void scatter_ws(const void* __restrict__ ei, int E, int sblk,
                           const float* __restrict__ W2) {
    if (blockIdx.x >= sblk) {
        int idx = (blockIdx.x - sblk) * 256 + threadIdx.x;
        if (idx < 16384) w_split_elem(W2, idx);
        return;
    }
    __shared__ int s64;
    int is64 = detect64_local(ei, &s64);
    int i = blockIdx.x * blockDim.x + threadIdx.x;
    if (i >= E) return;
    int si, di;
    if (is64) {
        const long long* p = (const long long*)ei;
        si = (int)p[i];
        di = (int)p[(size_t)E + i];
    } else {
        const int* p = (const int*)ei;
        si = p[i];
        di = p[(size_t)E + i];
    }
    int pos = atomicAdd(&d_cursor[di], 1);
    d_csr[pos] = si;
}

// ---------------------------------------------------------------------------
// Persistent HMMA GEMM: gout[row] = fp16( in[row] @ W )  (no dinv here).
// 64-row tiles, 8 warps (warp tile 32x32), 2 blocks/SM (16 MMA warps/SM).
__global__ void __launch_bounds__(256, 2)
gemm_tc(const float* __restrict__ in, __half* __restrict__ gout,
        int n, int ntiles) {
    extern __shared__ char dsm[];
    char* sBh = dsm;
    char* sBl = dsm + T_SH;
    char* sAh = dsm + 2 * T_SH;
    char* sAl = dsm + 2 * T_SH + A_SH;

    const int tid = threadIdx.x;
    const int wid = tid >> 5;
    const int lid = tid & 31;

    // --- Stage B once: linear copy of pre-split global images ---
    {
        const float4* wh = (const float4*)d_Whi;
        const float4* wl = (const float4*)d_Wlo;
        float4* bh = (float4*)sBh;
        float4* bl = (float4*)sBl;
        for (int i = tid; i < T_SH / 16; i += 256) { bh[i] = wh[i]; bl[i] = wl[i]; }
    }

    // --- Warp tiling: warp tile 32 rows x 32 cols ---
    const int mrow0 = (wid >> 2) * 32;     // 0 or 32
    const int ncol0 = (wid & 3) * 32;      // 0,32,64,96
    const int sel   = lid >> 3;
    const int rowIn = lid & 7;
    const uint32_t aoff =
        (uint32_t)(((mrow0 + rowIn + (sel & 1) * 8) * BSTRIDE + (sel >> 1) * 8) * 2);
    const uint32_t boff =
        (uint32_t)(((ncol0 + (sel >> 1) * 8 + rowIn) * BSTRIDE + (sel & 1) * 8) * 2);
    const uint32_t aHi = smem_u32(sAh) + aoff;
    const uint32_t aLo = smem_u32(sAl) + aoff;
    const uint32_t bHi = smem_u32(sBh) + boff;
    const uint32_t bLo = smem_u32(sBl) + boff;

    // A staging: thread -> (row, col-quarter)
    const int ar = tid >> 2;           // 0..63
    const int ac = tid & 3;            // col quarter (32 cols)

    for (int t = blockIdx.x; t < ntiles; t += gridDim.x) {
        // --- Stage A tile: load fp32, split hi/lo bf16 ---
        {
            int gr = t * 64 + ar;
            if (gr >= n) gr = n - 1;
            const float4* src = (const float4*)(in + (size_t)gr * FD) + ac * 8;
            unsigned short* ah = (unsigned short*)sAh + ar * BSTRIDE + ac * 32;
            unsigned short* al = (unsigned short*)sAl + ar * BSTRIDE + ac * 32;
#pragma unroll
            for (int i = 0; i < 8; ++i) {
                float4 v = __ldg(src + i);
                __nv_bfloat16 h0 = __float2bfloat16_rn(v.x);
                __nv_bfloat16 h1 = __float2bfloat16_rn(v.y);
                __nv_bfloat16 h2 = __float2bfloat16_rn(v.z);
                __nv_bfloat16 h3 = __float2bfloat16_rn(v.w);
                *(uint32_t*)(ah + i * 4)     = (uint32_t)bfbits(h0) | ((uint32_t)bfbits(h1) << 16);
                *(uint32_t*)(ah + i * 4 + 2) = (uint32_t)bfbits(h2) | ((uint32_t)bfbits(h3) << 16);
                *(uint32_t*)(al + i * 4) =
                    (uint32_t)bfbits(__float2bfloat16_rn(v.x - __bfloat162float(h0))) |
                    ((uint32_t)bfbits(__float2bfloat16_rn(v.y - __bfloat162float(h1))) << 16);
                *(uint32_t*)(al + i * 4 + 2) =
                    (uint32_t)bfbits(__float2bfloat16_rn(v.z - __bfloat162float(h2))) |
                    ((uint32_t)bfbits(__float2bfloat16_rn(v.w - __bfloat162float(h3))) << 16);
            }
        }
        __syncthreads();

        // --- MMA phase (term-major) ---
        float acc[2][4][4];
#pragma unroll
        for (int i = 0; i < 2; ++i)
#pragma unroll
            for (int j = 0; j < 4; ++j)
#pragma unroll
                for (int q = 0; q < 4; ++q) acc[i][j][q] = 0.f;

#pragma unroll
        for (int ks = 0; ks < 8; ++ks) {
            const uint32_t kb = ks * 32;
            uint32_t ah[2][4], al[2][4], bh2[4][2], bl2[4][2];
#pragma unroll
            for (int i = 0; i < 2; ++i) {
                ldm_x4(ah[i], aHi + i * (16 * BSTRIDE * 2) + kb);
                ldm_x4(al[i], aLo + i * (16 * BSTRIDE * 2) + kb);
            }
#pragma unroll
            for (int j2 = 0; j2 < 2; ++j2) {
                uint32_t q[4];
                ldm_x4(q, bHi + j2 * (16 * BSTRIDE * 2) + kb);
                bh2[2 * j2][0] = q[0]; bh2[2 * j2][1] = q[1];
                bh2[2 * j2 + 1][0] = q[2]; bh2[2 * j2 + 1][1] = q[3];
                ldm_x4(q, bLo + j2 * (16 * BSTRIDE * 2) + kb);
                bl2[2 * j2][0] = q[0]; bl2[2 * j2][1] = q[1];
                bl2[2 * j2 + 1][0] = q[2]; bl2[2 * j2 + 1][1] = q[3];
            }
#pragma unroll
            for (int i = 0; i < 2; ++i)
#pragma unroll
                for (int j = 0; j < 4; ++j) mma_bf16(acc[i][j], ah[i], bh2[j]);
#pragma unroll
            for (int i = 0; i < 2; ++i)
#pragma unroll
                for (int j = 0; j < 4; ++j) mma_bf16(acc[i][j], ah[i], bl2[j]);
#pragma unroll
            for (int i = 0; i < 2; ++i)
#pragma unroll
                for (int j = 0; j < 4; ++j) mma_bf16(acc[i][j], al[i], bh2[j]);
        }

        // --- Epilogue: convert fp16, store ---
        {
            const int rb = t * 64 + mrow0 + (lid >> 2);
            const int cbase = ncol0 + 2 * (lid & 3);
#pragma unroll
            for (int i = 0; i < 2; ++i) {
                int r1 = rb + 16 * i;
                int r2 = r1 + 8;
#pragma unroll
                for (int j = 0; j < 4; ++j) {
                    int c = cbase + 8 * j;
                    if (r1 < n)
                        *(__half2*)(gout + (size_t)r1 * FD + c) =
                            __floats2half2_rn(acc[i][j][0], acc[i][j][1]);
                    if (r2 < n)
                        *(__half2*)(gout + (size_t)r2 * FD + c) =
                            __floats2half2_rn(acc[i][j][2], acc[i][j][3]);
                }
            }
        }
        __syncthreads();
    }
}

// ---------------------------------------------------------------------------
// Fused aggregate + epilogue: one warp per dst node, fp16 gather with per-src
// dinv scaling: out[d] = dinv[d]*(Σ dinv[s]·g[s] + dinv[d]·g[d]) + b [+relu]
__global__ void __launch_bounds__(256)
aggregate_csr(const __half* __restrict__ g, const float* __restrict__ bias,
              float* __restrict__ out, int n, int do_relu) {
    const int w = blockIdx.x * 8 + (threadIdx.x >> 5);
    if (w >= n) return;
    const int lane = threadIdx.x & 31;

    const uint2* gw = (const uint2*)g + lane;   // row stride: 32 uint2
    const float dv = d_dinv[w];

    float acc0, acc1, acc2, acc3;
    {
        uint2 raw = __ldg(gw + (size_t)w * 32);  // self-loop term
        float2 f0 = __half22float2(*(__half2*)&raw.x);
        float2 f1 = __half22float2(*(__half2*)&raw.y);
        acc0 = dv * f0.x; acc1 = dv * f0.y; acc2 = dv * f1.x; acc3 = dv * f1.y;
    }

    int e = d_off[w];
    const int eend = d_off[w + 1];
    for (; e + 4 <= eend; e += 4) {
        int s0 = __ldg(&d_csr[e]);
        int s1 = __ldg(&d_csr[e + 1]);
        int s2 = __ldg(&d_csr[e + 2]);
        int s3 = __ldg(&d_csr[e + 3]);
        uint2 ra = __ldg(gw + (size_t)s0 * 32);
        uint2 rb = __ldg(gw + (size_t)s1 * 32);
        uint2 rc = __ldg(gw + (size_t)s2 * 32);
        uint2 rd = __ldg(gw + (size_t)s3 * 32);
        float w0 = __ldg(&d_dinv[s0]);
        float w1 = __ldg(&d_dinv[s1]);
        float w2 = __ldg(&d_dinv[s2]);
        float w3 = __ldg(&d_dinv[s3]);
        float2 a0 = __half22float2(*(__half2*)&ra.x), a1 = __half22float2(*(__half2*)&ra.y);
        float2 b0 = __half22float2(*(__half2*)&rb.x), b1 = __half22float2(*(__half2*)&rb.y);
        float2 c0 = __half22float2(*(__half2*)&rc.x), c1 = __half22float2(*(__half2*)&rc.y);
        float2 d0 = __half22float2(*(__half2*)&rd.x), d1 = __half22float2(*(__half2*)&rd.y);
        acc0 += w0 * a0.x + w1 * b0.x + w2 * c0.x + w3 * d0.x;
        acc1 += w0 * a0.y + w1 * b0.y + w2 * c0.y + w3 * d0.y;
        acc2 += w0 * a1.x + w1 * b1.x + w2 * c1.x + w3 * d1.x;
        acc3 += w0 * a1.y + w1 * b1.y + w2 * c1.y + w3 * d1.y;
    }
    for (; e < eend; ++e) {
        int s0 = __ldg(&d_csr[e]);
        uint2 ra = __ldg(gw + (size_t)s0 * 32);
        float w0 = __ldg(&d_dinv[s0]);
        float2 a0 = __half22float2(*(__half2*)&ra.x), a1 = __half22float2(*(__half2*)&ra.y);
        acc0 += w0 * a0.x; acc1 += w0 * a0.y; acc2 += w0 * a1.x; acc3 += w0 * a1.y;
    }

    float4 bs = __ldg((const float4*)bias + lane);
    float4 r;
    r.x = dv * acc0 + bs.x;
    r.y = dv * acc1 + bs.y;
    r.z = dv * acc2 + bs.z;
    r.w = dv * acc3 + bs.w;
    if (do_relu) {
        r.x = fmaxf(r.x, 0.f); r.y = fmaxf(r.y, 0.f);
        r.z = fmaxf(r.z, 0.f); r.w = fmaxf(r.w, 0.f);
    }
    ((float4*)(out + (size_t)w * FD))[lane] = r;
}

// ---------------------------------------------------------------------------
extern "C" void kernel_launch(void* const* d_in, const int* in_sizes, int n_in,
                              void* d_out, int out_size) {
    const float* x  = (const float*)d_in[0];
    const void*  ei = d_in[1];
    const float* W1 = (const float*)d_in[2];
    const float* b1 = (const float*)d_in[3];
    const float* W2 = (const float*)d_in[4];
    const float* b2 = (const float*)d_in[5];
    float* out = (float*)d_out;

    int n = in_sizes[0] / FD;
    if (n > NMAX) n = NMAX;
    int E = in_sizes[1] / 2;
    if (E > EMAX) E = EMAX;

    float *bufA, *bufB;
    int* degi;
    cudaGetSymbolAddress((void**)&bufA, d_bufA);
    cudaGetSymbolAddress((void**)&bufB, d_bufB);
    cudaGetSymbolAddress((void**)&degi, d_degi);
    __half* gbuf = (__half*)bufA;

    cudaFuncSetAttribute(gemm_tc,
                         cudaFuncAttributeMaxDynamicSharedMemorySize, GEMM_SMEM);

    // Side stream + events: created once on the FIRST call (the eager
    // correctness run, outside graph capture); reused during capture where
    // the event record/wait pattern becomes graph fork/join edges.
    static cudaStream_t s_side = []() {
        cudaStream_t s;
        cudaStreamCreateWithFlags(&s, cudaStreamNonBlocking);
        return s;
    }();
    static cudaEvent_t s_fork = []() {
        cudaEvent_t e;
        cudaEventCreateWithFlags(&e, cudaEventDisableTiming);
        return e;
    }();
    static cudaEvent_t s_join = []() {
        cudaEvent_t e;
        cudaEventCreateWithFlags(&e, cudaEventDisableTiming);
        return e;
    }();

    const int ntiles = (n + 63) / 64;
    const int ggrid = (ntiles < 2 * NSM) ? ntiles : 2 * NSM;
    const int sblk = (E + 255) / 256;

    // ---- fork: CSR build + dinv + W2 split on side stream ----
    cudaEventRecord(s_fork, 0);
    cudaStreamWaitEvent(s_side, s_fork, 0);
    cudaMemsetAsync(degi, 0, (size_t)n * sizeof(int), s_side);
    deg_count<<<(E + 255) / 256, 256, 0, s_side>>>(ei, E);
    scan_partial<<<SCAN_NBLK, SCAN_T, 0, s_side>>>(n);
    scan_blocksums<<<1, 32, 0, s_side>>>(SCAN_NBLK);
    scan_add<<<(n + 255) / 256, 256, 0, s_side>>>(n, E);
    scatter_ws<<<sblk + 64, 256, 0, s_side>>>(ei, E, sblk, W2);
    cudaEventRecord(s_join, s_side);

    // ---- main: W1 split -> layer-1 GEMM (overlaps the side branch) ----
    w_split<<<64, 256>>>(W1);
    gemm_tc<<<ggrid, 256, GEMM_SMEM>>>(x, gbuf, n, ntiles);

    // ---- join: aggregate needs CSR + dinv + g1 ----
    cudaStreamWaitEvent(0, s_join, 0);
    aggregate_csr<<<(n + 7) / 8, 256>>>(gbuf, b1, bufB, n, 1);

    // ---- layer 2 (W2 images ready via join) ----
    gemm_tc<<<ggrid, 256, GEMM_SMEM>>>(bufB, gbuf, n, ntiles);
    aggregate_csr<<<(n + 7) / 8, 256>>>(gbuf, b2, out, n, 0);
}

// round 13
// speedup vs baseline: 1.0656x; 1.0656x over previous
#include <cuda_runtime.h>
#include <cuda_bf16.h>
#include <cuda_fp16.h>
#include <cstdint>

// GNN_9869834846215: two-layer cached GCN.
//   g = h W (fp16)     -- cp.async-pipelined HMMA bf16x2-split GEMM
//   out[d] = dinv[d]*(Σ dinv[s]·g[s] + dinv[d]·g[d]) + b
// GEMM inputs are pre-split bf16 hi/lo global images. W1/W2 have SEPARATE
// image buffers (W2 split on the side stream must not race gemm1's B reads).

#define NMAX 100000
#define EMAX 1700000
#define FD 128
#define SCAN_T 1024
#define SCAN_C 4096
#define SCAN_NBLK 25
#define NSM 148

#define BSTRIDE 136                        // bf16 smem row stride (272B)
#define B_SH (128 * BSTRIDE * 2)           // 34816 B per B image
#define A_STG (32 * BSTRIDE * 2)           // 8704 B per 32-row A image
#define GEMM_SMEM (2 * B_SH + 2 * 2 * A_STG)  // 104448 -> 2 blocks/SM

// Scratch (__device__ globals per allocation-free rule)
__device__ float d_dinv[NMAX];
__device__ float d_bufA[(size_t)NMAX * FD];            // g (fp16 view)
__device__ __align__(16) unsigned short d_xhi[(size_t)NMAX * FD];
__device__ __align__(16) unsigned short d_xlo[(size_t)NMAX * FD];
__device__ __align__(16) unsigned short d_hhi[(size_t)NMAX * FD];
__device__ __align__(16) unsigned short d_hlo[(size_t)NMAX * FD];
__device__ int   d_degi[NMAX];
__device__ int   d_off[NMAX + 1];
__device__ int   d_cursor[NMAX];
__device__ int   d_csr[EMAX];
__device__ int   d_blocksums[32];
// Separate W^T bf16 hi/lo images for W1 and W2 ([n][k], row stride BSTRIDE)
__device__ __align__(16) unsigned short d_W1hi[128 * BSTRIDE];
__device__ __align__(16) unsigned short d_W1lo[128 * BSTRIDE];
__device__ __align__(16) unsigned short d_W2hi[128 * BSTRIDE];
__device__ __align__(16) unsigned short d_W2lo[128 * BSTRIDE];

// ---------------------------------------------------------------------------
__device__ __forceinline__ uint32_t smem_u32(const void* p) {
    uint32_t a;
    asm("{ .reg .u64 t; cvta.to.shared.u64 t, %1; cvt.u32.u64 %0, t; }"
        : "=r"(a) : "l"(p));
    return a;
}
__device__ __forceinline__ void ldm_x4(uint32_t* r, uint32_t addr) {
    asm volatile("ldmatrix.sync.aligned.m8n8.x4.shared.b16 {%0,%1,%2,%3}, [%4];"
                 : "=r"(r[0]), "=r"(r[1]), "=r"(r[2]), "=r"(r[3]) : "r"(addr));
}
__device__ __forceinline__ void mma_bf16(float* c, const uint32_t* a,
                                         const uint32_t* b) {
    asm volatile(
        "mma.sync.aligned.m16n8k16.row.col.f32.bf16.bf16.f32 "
        "{%0,%1,%2,%3}, {%4,%5,%6,%7}, {%8,%9}, {%0,%1,%2,%3};"
        : "+f"(c[0]), "+f"(c[1]), "+f"(c[2]), "+f"(c[3])
        : "r"(a[0]), "r"(a[1]), "r"(a[2]), "r"(a[3]), "r"(b[0]), "r"(b[1]));
}
__device__ __forceinline__ void cp16(uint32_t smem, const void* g) {
    asm volatile("cp.async.cg.shared.global [%0], [%1], 16;"
                 :: "r"(smem), "l"(g) : "memory");
}
__device__ __forceinline__ unsigned short bfbits(__nv_bfloat16 h) {
    return __bfloat16_as_ushort(h);
}
__device__ __forceinline__ int detect64_local(const void* ei, int* s64) {
    if (threadIdx.x == 0) {
        const int2* p = (const int2*)ei;
        int is64 = 1;
        for (int j = 0; j < 64; ++j)
            if (p[j].y != 0) { is64 = 0; break; }
        *s64 = is64;
    }
    __syncthreads();
    return *s64;
}

// ---------------------------------------------------------------------------
__device__ __forceinline__ void w_split_elem(const float* W,
                                             unsigned short* hi,
                                             unsigned short* lo, int idx) {
    int nn = idx & 127, kk = idx >> 7;
    float v = W[kk * FD + nn];
    __nv_bfloat16 h = __float2bfloat16_rn(v);
    __nv_bfloat16 l = __float2bfloat16_rn(v - __bfloat162float(h));
    hi[nn * BSTRIDE + kk] = bfbits(h);
    lo[nn * BSTRIDE + kk] = bfbits(l);
}

__global__ void w_split1(const float* __restrict__ W) {
    int idx = blockIdx.x * 256 + threadIdx.x;
    if (idx < 16384) w_split_elem(W, d_W1hi, d_W1lo, idx);
}

// Prepass: split fp32 rows into bf16 hi/lo global images (8 floats/iter).
__global__ void split_inp(const float* __restrict__ in,
                          unsigned short* __restrict__ hi,
                          unsigned short* __restrict__ lo, int total8) {
    for (int i = blockIdx.x * blockDim.x + threadIdx.x; i < total8;
         i += gridDim.x * blockDim.x) {
        const float4* src = (const float4*)in + 2 * (size_t)i;
        float4 v0 = __ldg(src);
        float4 v1 = __ldg(src + 1);
        float f[8] = {v0.x, v0.y, v0.z, v0.w, v1.x, v1.y, v1.z, v1.w};
        alignas(16) unsigned short hb[8];
        alignas(16) unsigned short lb[8];
#pragma unroll
        for (int q = 0; q < 8; ++q) {
            __nv_bfloat16 h = __float2bfloat16_rn(f[q]);
            hb[q] = bfbits(h);
            lb[q] = bfbits(__float2bfloat16_rn(f[q] - __bfloat162float(h)));
        }
        ((uint4*)hi)[i] = *(uint4*)hb;
        ((uint4*)lo)[i] = *(uint4*)lb;
    }
}

__global__ void deg_count(const void* __restrict__ ei, int E) {
    __shared__ int s64;
    int is64 = detect64_local(ei, &s64);
    int i = blockIdx.x * blockDim.x + threadIdx.x;
    if (i >= E) return;
    int d = is64 ? (int)((const long long*)ei)[(size_t)E + i]
                 : ((const int*)ei)[(size_t)E + i];
    atomicAdd(&d_degi[d], 1);
}

__global__ void __launch_bounds__(SCAN_T)
scan_partial(int n) {
    __shared__ int ssum[SCAN_T];
    const int tid  = threadIdx.x;
    const int base = blockIdx.x * SCAN_C + tid * 4;
    int v[4];
#pragma unroll
    for (int i = 0; i < 4; ++i) {
        v[i] = (base + i < n) ? d_degi[base + i] : 0;
        if (base + i < n) d_dinv[base + i] = rsqrtf((float)v[i] + 1.0f);
    }
    int tsum = v[0] + v[1] + v[2] + v[3];
    ssum[tid] = tsum;
    __syncthreads();
    for (int off = 1; off < SCAN_T; off <<= 1) {
        int t = (tid >= off) ? ssum[tid - off] : 0;
        __syncthreads();
        ssum[tid] += t;
        __syncthreads();
    }
    int texcl = ssum[tid] - tsum;
    if (tid == SCAN_T - 1) d_blocksums[blockIdx.x] = ssum[tid];
    int run = texcl;
#pragma unroll
    for (int i = 0; i < 4; ++i) {
        if (base + i < n) d_off[base + i] = run;
        run += v[i];
    }
}

__global__ void scan_blocksums(int nblk) {
    int tid = threadIdx.x;
    int v = (tid < nblk) ? d_blocksums[tid] : 0;
    int orig = v;
#pragma unroll
    for (int o = 1; o < 32; o <<= 1) {
        int t = __shfl_up_sync(0xFFFFFFFFu, v, o);
        if (tid >= o) v += t;
    }
    if (tid < nblk) d_blocksums[tid] = v - orig;
}

__global__ void scan_add(int n, int E) {
    int i = blockIdx.x * blockDim.x + threadIdx.x;
    if (i < n) {
        int v = d_off[i] + d_blocksums[i / SCAN_C];
        d_off[i] = v;
        d_cursor[i] = v;
    }
    if (i == 0) d_off[n] = E;
}

// scatter + W2 split into the W2-ONLY image buffers (no race with gemm1).
__global__ void scatter_ws(const void* __restrict__ ei, int E, int sblk,
                           const float* __restrict__ W2) {
    if (blockIdx.x >= sblk) {
        int idx = (blockIdx.x - sblk) * 256 + threadIdx.x;
        if (idx < 16384) w_split_elem(W2, d_W2hi, d_W2lo, idx);
        return;
    }
    __shared__ int s64;
    int is64 = detect64_local(ei, &s64);
    int i = blockIdx.x * blockDim.x + threadIdx.x;
    if (i >= E) return;
    int si, di;
    if (is64) {
        const long long* p = (const long long*)ei;
        si = (int)p[i];
        di = (int)p[(size_t)E + i];
    } else {
        const int* p = (const int*)ei;
        si = p[i];
        di = p[(size_t)E + i];
    }
    int pos = atomicAdd(&d_cursor[di], 1);
    d_csr[pos] = si;
}

// ---------------------------------------------------------------------------
// cp.async-pipelined persistent HMMA GEMM.
//   gout[row] = fp16( A[row] @ W ),  A and W given as bf16 hi/lo images.
// 32-row tiles, warp tile 16x32, 2-stage A ring, 2 blocks/SM.
__global__ void __launch_bounds__(256, 2)
gemm_tc(const unsigned short* __restrict__ Ahi,
        const unsigned short* __restrict__ Alo,
        const unsigned short* __restrict__ Whi,
        const unsigned short* __restrict__ Wlo,
        __half* __restrict__ gout, int n, int ntiles) {
    extern __shared__ char dsm[];
    char* sBh = dsm;
    char* sBl = dsm + B_SH;
    const uint32_t aBase = smem_u32(dsm + 2 * B_SH);   // 2 stages x (hi, lo)

    const int tid = threadIdx.x;
    const int wid = tid >> 5;
    const int lid = tid & 31;

    // Stage B images once (linear copy).
    {
        const float4* wh = (const float4*)Whi;
        const float4* wl = (const float4*)Wlo;
        float4* bh = (float4*)sBh;
        float4* bl = (float4*)sBl;
        for (int i = tid; i < B_SH / 16; i += 256) { bh[i] = wh[i]; bl[i] = wl[i]; }
    }

    // Warp tiling: 16 rows x 32 cols.
    const int mrow0 = (wid >> 2) * 16;     // 0 or 16
    const int ncol0 = (wid & 3) * 32;      // 0,32,64,96
    const int sel   = lid >> 3;
    const int rowIn = lid & 7;
    const uint32_t aoff =
        (uint32_t)(((mrow0 + rowIn + (sel & 1) * 8) * BSTRIDE + (sel >> 1) * 8) * 2);
    const uint32_t boff =
        (uint32_t)(((ncol0 + (sel >> 1) * 8 + rowIn) * BSTRIDE + (sel & 1) * 8) * 2);
    const uint32_t bHi = smem_u32(sBh) + boff;
    const uint32_t bLo = smem_u32(sBl) + boff;

    // cp.async chunk mapping: 1024 chunks = 2 imgs x 32 rows x 16 chunks.
    auto issue = [&](int tt, int s) {
#pragma unroll
        for (int i = 0; i < 4; ++i) {
            int id  = tid + i * 256;
            int img = id >> 9;
            int rc  = id & 511;
            int r   = rc >> 4;
            int c   = rc & 15;
            int gr  = tt * 32 + r;
            if (gr >= n) gr = n - 1;
            const unsigned short* src =
                (img ? Alo : Ahi) + (size_t)gr * FD + c * 8;
            uint32_t dst = aBase + s * (2 * A_STG) + img * A_STG +
                           r * (BSTRIDE * 2) + c * 16;
            cp16(dst, src);
        }
        asm volatile("cp.async.commit_group;" ::: "memory");
    };

    int t = blockIdx.x;
    if (t < ntiles) issue(t, 0);
    int p = 0;

    for (; t < ntiles; t += gridDim.x) {
        const int tn = t + gridDim.x;
        if (tn < ntiles) {
            issue(tn, p ^ 1);
            asm volatile("cp.async.wait_group 1;" ::: "memory");
        } else {
            asm volatile("cp.async.wait_group 0;" ::: "memory");
        }
        __syncthreads();

        const uint32_t aHi = aBase + p * (2 * A_STG) + aoff;
        const uint32_t aLo = aHi + A_STG;

        float acc[4][4];
#pragma unroll
        for (int j = 0; j < 4; ++j)
#pragma unroll
            for (int q = 0; q < 4; ++q) acc[j][q] = 0.f;

#pragma unroll
        for (int ks = 0; ks < 8; ++ks) {
            const uint32_t kb = ks * 32;
            uint32_t ah[4], al[4], bh2[4][2], bl2[4][2];
            ldm_x4(ah, aHi + kb);
            ldm_x4(al, aLo + kb);
#pragma unroll
            for (int j2 = 0; j2 < 2; ++j2) {
                uint32_t q[4];
                ldm_x4(q, bHi + j2 * (16 * BSTRIDE * 2) + kb);
                bh2[2 * j2][0] = q[0]; bh2[2 * j2][1] = q[1];
                bh2[2 * j2 + 1][0] = q[2]; bh2[2 * j2 + 1][1] = q[3];
                ldm_x4(q, bLo + j2 * (16 * BSTRIDE * 2) + kb);
                bl2[2 * j2][0] = q[0]; bl2[2 * j2][1] = q[1];
                bl2[2 * j2 + 1][0] = q[2]; bl2[2 * j2 + 1][1] = q[3];
            }
#pragma unroll
            for (int j = 0; j < 4; ++j) mma_bf16(acc[j], ah, bh2[j]);
#pragma unroll
            for (int j = 0; j < 4; ++j) mma_bf16(acc[j], ah, bl2[j]);
#pragma unroll
            for (int j = 0; j < 4; ++j) mma_bf16(acc[j], al, bh2[j]);
        }

        // Epilogue: fp16 store.
        {
            const int r1 = t * 32 + mrow0 + (lid >> 2);
            const int r2 = r1 + 8;
            const int cbase = ncol0 + 2 * (lid & 3);
#pragma unroll
            for (int j = 0; j < 4; ++j) {
                int c = cbase + 8 * j;
                if (r1 < n)
                    *(__half2*)(gout + (size_t)r1 * FD + c) =
                        __floats2half2_rn(acc[j][0], acc[j][1]);
                if (r2 < n)
                    *(__half2*)(gout + (size_t)r2 * FD + c) =
                        __floats2half2_rn(acc[j][2], acc[j][3]);
            }
        }
        __syncthreads();
        p ^= 1;
    }
}

// ---------------------------------------------------------------------------
// Fused aggregate: one warp per dst node, fp16 gather, per-src dinv scaling.
// mode 1: relu, write h as bf16 hi/lo images. mode 0: write fp32 out.
__global__ void __launch_bounds__(256)
aggregate_csr(const __half* __restrict__ g, const float* __restrict__ bias,
              float* __restrict__ out, unsigned short* __restrict__ ohi,
              unsigned short* __restrict__ olo, int n, int mode) {
    const int w = blockIdx.x * 8 + (threadIdx.x >> 5);
    if (w >= n) return;
    const int lane = threadIdx.x & 31;

    const uint2* gw = (const uint2*)g + lane;
    const float dv = d_dinv[w];

    float acc0, acc1, acc2, acc3;
    {
        uint2 raw = __ldg(gw + (size_t)w * 32);
        float2 f0 = __half22float2(*(__half2*)&raw.x);
        float2 f1 = __half22float2(*(__half2*)&raw.y);
        acc0 = dv * f0.x; acc1 = dv * f0.y; acc2 = dv * f1.x; acc3 = dv * f1.y;
    }

    int e = d_off[w];
    const int eend = d_off[w + 1];
    for (; e + 4 <= eend; e += 4) {
        int s0 = __ldg(&d_csr[e]);
        int s1 = __ldg(&d_csr[e + 1]);
        int s2 = __ldg(&d_csr[e + 2]);
        int s3 = __ldg(&d_csr[e + 3]);
        uint2 ra = __ldg(gw + (size_t)s0 * 32);
        uint2 rb = __ldg(gw + (size_t)s1 * 32);
        uint2 rc = __ldg(gw + (size_t)s2 * 32);
        uint2 rd = __ldg(gw + (size_t)s3 * 32);
        float w0 = __ldg(&d_dinv[s0]);
        float w1 = __ldg(&d_dinv[s1]);
        float w2 = __ldg(&d_dinv[s2]);
        float w3 = __ldg(&d_dinv[s3]);
        float2 a0 = __half22float2(*(__half2*)&ra.x), a1 = __half22float2(*(__half2*)&ra.y);
        float2 b0 = __half22float2(*(__half2*)&rb.x), b1 = __half22float2(*(__half2*)&rb.y);
        float2 c0 = __half22float2(*(__half2*)&rc.x), c1 = __half22float2(*(__half2*)&rc.y);
        float2 d0 = __half22float2(*(__half2*)&rd.x), d1 = __half22float2(*(__half2*)&rd.y);
        acc0 += w0 * a0.x + w1 * b0.x + w2 * c0.x + w3 * d0.x;
        acc1 += w0 * a0.y + w1 * b0.y + w2 * c0.y + w3 * d0.y;
        acc2 += w0 * a1.x + w1 * b1.x + w2 * c1.x + w3 * d1.x;
        acc3 += w0 * a1.y + w1 * b1.y + w2 * c1.y + w3 * d1.y;
    }
    for (; e < eend; ++e) {
        int s0 = __ldg(&d_csr[e]);
        uint2 ra = __ldg(gw + (size_t)s0 * 32);
        float w0 = __ldg(&d_dinv[s0]);
        float2 a0 = __half22float2(*(__half2*)&ra.x), a1 = __half22float2(*(__half2*)&ra.y);
        acc0 += w0 * a0.x; acc1 += w0 * a0.y; acc2 += w0 * a1.x; acc3 += w0 * a1.y;
    }

    float4 bs = __ldg((const float4*)bias + lane);
    float r0 = dv * acc0 + bs.x;
    float r1 = dv * acc1 + bs.y;
    float r2 = dv * acc2 + bs.z;
    float r3 = dv * acc3 + bs.w;

    if (mode) {
        r0 = fmaxf(r0, 0.f); r1 = fmaxf(r1, 0.f);
        r2 = fmaxf(r2, 0.f); r3 = fmaxf(r3, 0.f);
        float f[4] = {r0, r1, r2, r3};
        alignas(8) unsigned short hb[4];
        alignas(8) unsigned short lb[4];
#pragma unroll
        for (int q = 0; q < 4; ++q) {
            __nv_bfloat16 h = __float2bfloat16_rn(f[q]);
            hb[q] = bfbits(h);
            lb[q] = bfbits(__float2bfloat16_rn(f[q] - __bfloat162float(h)));
        }
        *(uint2*)(ohi + (size_t)w * FD + lane * 4) = *(uint2*)hb;
        *(uint2*)(olo + (size_t)w * FD + lane * 4) = *(uint2*)lb;
    } else {
        ((float4*)(out + (size_t)w * FD))[lane] = make_float4(r0, r1, r2, r3);
    }
}

// ---------------------------------------------------------------------------
extern "C" void kernel_launch(void* const* d_in, const int* in_sizes, int n_in,
                              void* d_out, int out_size) {
    const float* x  = (const float*)d_in[0];
    const void*  ei = d_in[1];
    const float* W1 = (const float*)d_in[2];
    const float* b1 = (const float*)d_in[3];
    const float* W2 = (const float*)d_in[4];
    const float* b2 = (const float*)d_in[5];
    float* out = (float*)d_out;

    int n = in_sizes[0] / FD;
    if (n > NMAX) n = NMAX;
    int E = in_sizes[1] / 2;
    if (E > EMAX) E = EMAX;

    float* bufA;
    int* degi;
    unsigned short *xhi, *xlo, *hhi, *hlo, *w1hi, *w1lo, *w2hi, *w2lo;
    cudaGetSymbolAddress((void**)&bufA, d_bufA);
    cudaGetSymbolAddress((void**)&degi, d_degi);
    cudaGetSymbolAddress((void**)&xhi, d_xhi);
    cudaGetSymbolAddress((void**)&xlo, d_xlo);
    cudaGetSymbolAddress((void**)&hhi, d_hhi);
    cudaGetSymbolAddress((void**)&hlo, d_hlo);
    cudaGetSymbolAddress((void**)&w1hi, d_W1hi);
    cudaGetSymbolAddress((void**)&w1lo, d_W1lo);
    cudaGetSymbolAddress((void**)&w2hi, d_W2hi);
    cudaGetSymbolAddress((void**)&w2lo, d_W2lo);
    __half* gbuf = (__half*)bufA;

    cudaFuncSetAttribute(gemm_tc,
                         cudaFuncAttributeMaxDynamicSharedMemorySize, GEMM_SMEM);

    static cudaStream_t s_side = []() {
        cudaStream_t s;
        cudaStreamCreateWithFlags(&s, cudaStreamNonBlocking);
        return s;
    }();
    static cudaEvent_t s_fork = []() {
        cudaEvent_t e;
        cudaEventCreateWithFlags(&e, cudaEventDisableTiming);
        return e;
    }();
    static cudaEvent_t s_join = []() {
        cudaEvent_t e;
        cudaEventCreateWithFlags(&e, cudaEventDisableTiming);
        return e;
    }();

    const int ntiles = (n + 31) / 32;
    const int ggrid = (ntiles < 2 * NSM) ? ntiles : 2 * NSM;
    const int sblk = (E + 255) / 256;

    // ---- fork: CSR build + dinv + W2 split (into W2-only buffers) ----
    cudaEventRecord(s_fork, 0);
    cudaStreamWaitEvent(s_side, s_fork, 0);
    cudaMemsetAsync(degi, 0, (size_t)n * sizeof(int), s_side);
    deg_count<<<(E + 255) / 256, 256, 0, s_side>>>(ei, E);
    scan_partial<<<SCAN_NBLK, SCAN_T, 0, s_side>>>(n);
    scan_blocksums<<<1, 32, 0, s_side>>>(SCAN_NBLK);
    scan_add<<<(n + 255) / 256, 256, 0, s_side>>>(n, E);
    scatter_ws<<<sblk + 64, 256, 0, s_side>>>(ei, E, sblk, W2);
    cudaEventRecord(s_join, s_side);

    // ---- main: W1 split + x split -> layer-1 GEMM (W1 images only) ----
    w_split1<<<64, 256>>>(W1);
    split_inp<<<2 * NSM, 256>>>(x, xhi, xlo, n * 16);
    gemm_tc<<<ggrid, 256, GEMM_SMEM>>>(xhi, xlo, w1hi, w1lo, gbuf, n, ntiles);

    // ---- join: aggregate needs CSR + dinv + g1 ----
    cudaStreamWaitEvent(0, s_join, 0);
    aggregate_csr<<<(n + 7) / 8, 256>>>(gbuf, b1, nullptr, hhi, hlo, n, 1);

    // ---- layer 2 (W2 images ready via join) ----
    gemm_tc<<<ggrid, 256, GEMM_SMEM>>>(hhi, hlo, w2hi, w2lo, gbuf, n, ntiles);
    aggregate_csr<<<(n + 7) / 8, 256>>>(gbuf, b2, out, nullptr, nullptr, n, 0);
}

// round 14
// speedup vs baseline: 1.1092x; 1.0409x over previous
#include <cuda_runtime.h>
#include <cuda_bf16.h>
#include <cuda_fp16.h>
#include <cstdint>

// GNN_9869834846215: two-layer cached GCN.
//   g = dinv ⊙ (h W) (fp16)  -- cp.async-pipelined HMMA bf16x2-split GEMM
//   out[d] = dinv[d]*(Σ_{s∈N(d)} g[s] + g[d]) + b
// GEMM inputs are pre-split bf16 hi/lo global images; CSR chain on a side
// stream with dependency-precise events (gemm1 waits only for dinv).

#define NMAX 100000
#define EMAX 1700000
#define FD 128
#define SCAN_T 1024
#define SCAN_C 4096
#define SCAN_NBLK 25
#define NSM 148

#define BSTRIDE 136                        // bf16 smem row stride (272B)
#define B_SH (128 * BSTRIDE * 2)           // 34816 B per B image
#define A_STG (32 * BSTRIDE * 2)           // 8704 B per 32-row A image
#define GEMM_SMEM (2 * B_SH + 2 * 2 * A_STG)  // 104448 -> 2 blocks/SM

// Scratch (__device__ globals per allocation-free rule)
__device__ float d_dinv[NMAX];
__device__ float d_bufA[(size_t)NMAX * FD];            // g (fp16 view)
__device__ __align__(16) unsigned short d_xhi[(size_t)NMAX * FD];
__device__ __align__(16) unsigned short d_xlo[(size_t)NMAX * FD];
__device__ __align__(16) unsigned short d_hhi[(size_t)NMAX * FD];
__device__ __align__(16) unsigned short d_hlo[(size_t)NMAX * FD];
__device__ int   d_degi[NMAX];
__device__ int   d_off[NMAX + 1];
__device__ int   d_cursor[NMAX];
__device__ int   d_csr[EMAX];
__device__ int   d_blocksums[32];
// Separate W^T bf16 hi/lo images for W1 and W2 ([n][k], row stride BSTRIDE)
__device__ __align__(16) unsigned short d_W1hi[128 * BSTRIDE];
__device__ __align__(16) unsigned short d_W1lo[128 * BSTRIDE];
__device__ __align__(16) unsigned short d_W2hi[128 * BSTRIDE];
__device__ __align__(16) unsigned short d_W2lo[128 * BSTRIDE];

// ---------------------------------------------------------------------------
__device__ __forceinline__ uint32_t smem_u32(const void* p) {
    uint32_t a;
    asm("{ .reg .u64 t; cvta.to.shared.u64 t, %1; cvt.u32.u64 %0, t; }"
        : "=r"(a) : "l"(p));
    return a;
}
__device__ __forceinline__ void ldm_x4(uint32_t* r, uint32_t addr) {
    asm volatile("ldmatrix.sync.aligned.m8n8.x4.shared.b16 {%0,%1,%2,%3}, [%4];"
                 : "=r"(r[0]), "=r"(r[1]), "=r"(r[2]), "=r"(r[3]) : "r"(addr));
}
__device__ __forceinline__ void mma_bf16(float* c, const uint32_t* a,
                                         const uint32_t* b) {
    asm volatile(
        "mma.sync.aligned.m16n8k16.row.col.f32.bf16.bf16.f32 "
        "{%0,%1,%2,%3}, {%4,%5,%6,%7}, {%8,%9}, {%0,%1,%2,%3};"
        : "+f"(c[0]), "+f"(c[1]), "+f"(c[2]), "+f"(c[3])
        : "r"(a[0]), "r"(a[1]), "r"(a[2]), "r"(a[3]), "r"(b[0]), "r"(b[1]));
}
__device__ __forceinline__ void cp16(uint32_t smem, const void* g) {
    asm volatile("cp.async.cg.shared.global [%0], [%1], 16;"
                 :: "r"(smem), "l"(g) : "memory");
}
__device__ __forceinline__ unsigned short bfbits(__nv_bfloat16 h) {
    return __bfloat16_as_ushort(h);
}
__device__ __forceinline__ int detect64_local(const void* ei, int* s64) {
    if (threadIdx.x == 0) {
        const int2* p = (const int2*)ei;
        int is64 = 1;
        for (int j = 0; j < 64; ++j)
            if (p[j].y != 0) { is64 = 0; break; }
        *s64 = is64;
    }
    __syncthreads();
    return *s64;
}

// ---------------------------------------------------------------------------
__device__ __forceinline__ void w_split_elem(const float* W,
                                             unsigned short* hi,
                                             unsigned short* lo, int idx) {
    int nn = idx & 127, kk = idx >> 7;
    float v = W[kk * FD + nn];
    __nv_bfloat16 h = __float2bfloat16_rn(v);
    __nv_bfloat16 l = __float2bfloat16_rn(v - __bfloat162float(h));
    hi[nn * BSTRIDE + kk] = bfbits(h);
    lo[nn * BSTRIDE + kk] = bfbits(l);
}

// Fused prepass: blocks [0,64) split W1; blocks [64,..) grid-stride split x.
__global__ void split_all(const float* __restrict__ x,
                          const float* __restrict__ W1,
                          unsigned short* __restrict__ hi,
                          unsigned short* __restrict__ lo, int total8) {
    if (blockIdx.x < 64) {
        int idx = blockIdx.x * 256 + threadIdx.x;
        if (idx < 16384) w_split_elem(W1, d_W1hi, d_W1lo, idx);
        return;
    }
    const int nb = gridDim.x - 64;
    for (int i = (blockIdx.x - 64) * blockDim.x + threadIdx.x; i < total8;
         i += nb * blockDim.x) {
        const float4* src = (const float4*)x + 2 * (size_t)i;
        float4 v0 = __ldg(src);
        float4 v1 = __ldg(src + 1);
        float f[8] = {v0.x, v0.y, v0.z, v0.w, v1.x, v1.y, v1.z, v1.w};
        alignas(16) unsigned short hb[8];
        alignas(16) unsigned short lb[8];
#pragma unroll
        for (int q = 0; q < 8; ++q) {
            __nv_bfloat16 h = __float2bfloat16_rn(f[q]);
            hb[q] = bfbits(h);
            lb[q] = bfbits(__float2bfloat16_rn(f[q] - __bfloat162float(h)));
        }
        ((uint4*)hi)[i] = *(uint4*)hb;
        ((uint4*)lo)[i] = *(uint4*)lb;
    }
}

__global__ void deg_count(const void* __restrict__ ei, int E) {
    __shared__ int s64;
    int is64 = detect64_local(ei, &s64);
    int i = blockIdx.x * blockDim.x + threadIdx.x;
    if (i >= E) return;
    int d = is64 ? (int)((const long long*)ei)[(size_t)E + i]
                 : ((const int*)ei)[(size_t)E + i];
    atomicAdd(&d_degi[d], 1);
}

__global__ void __launch_bounds__(SCAN_T)
scan_partial(int n) {
    __shared__ int ssum[SCAN_T];
    const int tid  = threadIdx.x;
    const int base = blockIdx.x * SCAN_C + tid * 4;
    int v[4];
#pragma unroll
    for (int i = 0; i < 4; ++i) {
        v[i] = (base + i < n) ? d_degi[base + i] : 0;
        if (base + i < n) d_dinv[base + i] = rsqrtf((float)v[i] + 1.0f);
    }
    int tsum = v[0] + v[1] + v[2] + v[3];
    ssum[tid] = tsum;
    __syncthreads();
    for (int off = 1; off < SCAN_T; off <<= 1) {
        int t = (tid >= off) ? ssum[tid - off] : 0;
        __syncthreads();
        ssum[tid] += t;
        __syncthreads();
    }
    int texcl = ssum[tid] - tsum;
    if (tid == SCAN_T - 1) d_blocksums[blockIdx.x] = ssum[tid];
    int run = texcl;
#pragma unroll
    for (int i = 0; i < 4; ++i) {
        if (base + i < n) d_off[base + i] = run;
        run += v[i];
    }
}

__global__ void scan_blocksums(int nblk) {
    int tid = threadIdx.x;
    int v = (tid < nblk) ? d_blocksums[tid] : 0;
    int orig = v;
#pragma unroll
    for (int o = 1; o < 32; o <<= 1) {
        int t = __shfl_up_sync(0xFFFFFFFFu, v, o);
        if (tid >= o) v += t;
    }
    if (tid < nblk) d_blocksums[tid] = v - orig;
}

__global__ void scan_add(int n, int E) {
    int i = blockIdx.x * blockDim.x + threadIdx.x;
    if (i < n) {
        int v = d_off[i] + d_blocksums[i / SCAN_C];
        d_off[i] = v;
        d_cursor[i] = v;
    }
    if (i == 0) d_off[n] = E;
}

// scatter + W2 split into the W2-ONLY image buffers (no race with gemm1).
__global__ void scatter_ws(const void* __restrict__ ei, int E, int sblk,
                           const float* __restrict__ W2) {
    if (blockIdx.x >= sblk) {
        int idx = (blockIdx.x - sblk) * 256 + threadIdx.x;
        if (idx < 16384) w_split_elem(W2, d_W2hi, d_W2lo, idx);
        return;
    }
    __shared__ int s64;
    int is64 = detect64_local(ei, &s64);
    int i = blockIdx.x * blockDim.x + threadIdx.x;
    if (i >= E) return;
    int si, di;
    if (is64) {
        const long long* p = (const long long*)ei;
        si = (int)p[i];
        di = (int)p[(size_t)E + i];
    } else {
        const int* p = (const int*)ei;
        si = p[i];
        di = p[(size_t)E + i];
    }
    int pos = atomicAdd(&d_cursor[di], 1);
    d_csr[pos] = si;
}

// ---------------------------------------------------------------------------
// cp.async-pipelined persistent HMMA GEMM.
//   gout[row] = fp16( dinv[row] * (A[row] @ W) ),  A/W as bf16 hi/lo images.
// 32-row tiles, warp tile 16x32, 2-stage A ring, 2 blocks/SM.
__global__ void __launch_bounds__(256, 2)
gemm_tc(const unsigned short* __restrict__ Ahi,
        const unsigned short* __restrict__ Alo,
        const unsigned short* __restrict__ Whi,
        const unsigned short* __restrict__ Wlo,
        __half* __restrict__ gout, int n, int ntiles) {
    extern __shared__ char dsm[];
    char* sBh = dsm;
    char* sBl = dsm + B_SH;
    const uint32_t aBase = smem_u32(dsm + 2 * B_SH);   // 2 stages x (hi, lo)

    const int tid = threadIdx.x;
    const int wid = tid >> 5;
    const int lid = tid & 31;

    // Stage B images once (linear copy).
    {
        const float4* wh = (const float4*)Whi;
        const float4* wl = (const float4*)Wlo;
        float4* bh = (float4*)sBh;
        float4* bl = (float4*)sBl;
        for (int i = tid; i < B_SH / 16; i += 256) { bh[i] = wh[i]; bl[i] = wl[i]; }
    }

    // Warp tiling: 16 rows x 32 cols.
    const int mrow0 = (wid >> 2) * 16;     // 0 or 16
    const int ncol0 = (wid & 3) * 32;      // 0,32,64,96
    const int sel   = lid >> 3;
    const int rowIn = lid & 7;
    const uint32_t aoff =
        (uint32_t)(((mrow0 + rowIn + (sel & 1) * 8) * BSTRIDE + (sel >> 1) * 8) * 2);
    const uint32_t boff =
        (uint32_t)(((ncol0 + (sel >> 1) * 8 + rowIn) * BSTRIDE + (sel & 1) * 8) * 2);
    const uint32_t bHi = smem_u32(sBh) + boff;
    const uint32_t bLo = smem_u32(sBl) + boff;

    // cp.async chunk mapping: 1024 chunks = 2 imgs x 32 rows x 16 chunks.
    auto issue = [&](int tt, int s) {
#pragma unroll
        for (int i = 0; i < 4; ++i) {
            int id  = tid + i * 256;
            int img = id >> 9;
            int rc  = id & 511;
            int r   = rc >> 4;
            int c   = rc & 15;
            int gr  = tt * 32 + r;
            if (gr >= n) gr = n - 1;
            const unsigned short* src =
                (img ? Alo : Ahi) + (size_t)gr * FD + c * 8;
            uint32_t dst = aBase + s * (2 * A_STG) + img * A_STG +
                           r * (BSTRIDE * 2) + c * 16;
            cp16(dst, src);
        }
        asm volatile("cp.async.commit_group;" ::: "memory");
    };

    int t = blockIdx.x;
    if (t < ntiles) issue(t, 0);
    int p = 0;

    for (; t < ntiles; t += gridDim.x) {
        const int tn = t + gridDim.x;
        if (tn < ntiles) {
            issue(tn, p ^ 1);
            asm volatile("cp.async.wait_group 1;" ::: "memory");
        } else {
            asm volatile("cp.async.wait_group 0;" ::: "memory");
        }
        __syncthreads();

        const uint32_t aHi = aBase + p * (2 * A_STG) + aoff;
        const uint32_t aLo = aHi + A_STG;

        float acc[4][4];
#pragma unroll
        for (int j = 0; j < 4; ++j)
#pragma unroll
            for (int q = 0; q < 4; ++q) acc[j][q] = 0.f;

#pragma unroll
        for (int ks = 0; ks < 8; ++ks) {
            const uint32_t kb = ks * 32;
            uint32_t ah[4], al[4], bh2[4][2], bl2[4][2];
            ldm_x4(ah, aHi + kb);
            ldm_x4(al, aLo + kb);
#pragma unroll
            for (int j2 = 0; j2 < 2; ++j2) {
                uint32_t q[4];
                ldm_x4(q, bHi + j2 * (16 * BSTRIDE * 2) + kb);
                bh2[2 * j2][0] = q[0]; bh2[2 * j2][1] = q[1];
                bh2[2 * j2 + 1][0] = q[2]; bh2[2 * j2 + 1][1] = q[3];
                ldm_x4(q, bLo + j2 * (16 * BSTRIDE * 2) + kb);
                bl2[2 * j2][0] = q[0]; bl2[2 * j2][1] = q[1];
                bl2[2 * j2 + 1][0] = q[2]; bl2[2 * j2 + 1][1] = q[3];
            }
#pragma unroll
            for (int j = 0; j < 4; ++j) mma_bf16(acc[j], ah, bh2[j]);
#pragma unroll
            for (int j = 0; j < 4; ++j) mma_bf16(acc[j], ah, bl2[j]);
#pragma unroll
            for (int j = 0; j < 4; ++j) mma_bf16(acc[j], al, bh2[j]);
        }

        // Epilogue: scale by dinv[row], convert fp16, store.
        {
            const int r1 = t * 32 + mrow0 + (lid >> 2);
            const int r2 = r1 + 8;
            const int cbase = ncol0 + 2 * (lid & 3);
            const float dv1 = (r1 < n) ? d_dinv[r1] : 0.f;
            const float dv2 = (r2 < n) ? d_dinv[r2] : 0.f;
#pragma unroll
            for (int j = 0; j < 4; ++j) {
                int c = cbase + 8 * j;
                if (r1 < n)
                    *(__half2*)(gout + (size_t)r1 * FD + c) =
                        __floats2half2_rn(acc[j][0] * dv1, acc[j][1] * dv1);
                if (r2 < n)
                    *(__half2*)(gout + (size_t)r2 * FD + c) =
                        __floats2half2_rn(acc[j][2] * dv2, acc[j][3] * dv2);
            }
        }
        __syncthreads();
        p ^= 1;
    }
}

// ---------------------------------------------------------------------------
// Fused aggregate: one warp per dst node, fp16 gather (g pre-scaled by dinv).
//   out[d] = dinv[d]*(Σ_{s∈CSR(d)} g[s] + g[d]) + b
// mode 1: relu, write h as bf16 hi/lo images. mode 0: write fp32 out.
__global__ void __launch_bounds__(256)
aggregate_csr(const __half* __restrict__ g, const float* __restrict__ bias,
              float* __restrict__ out, unsigned short* __restrict__ ohi,
              unsigned short* __restrict__ olo, int n, int mode) {
    const int w = blockIdx.x * 8 + (threadIdx.x >> 5);
    if (w >= n) return;
    const int lane = threadIdx.x & 31;

    const uint2* gw = (const uint2*)g + lane;

    float acc0, acc1, acc2, acc3;
    {
        uint2 raw = __ldg(gw + (size_t)w * 32);
        float2 f0 = __half22float2(*(__half2*)&raw.x);
        float2 f1 = __half22float2(*(__half2*)&raw.y);
        acc0 = f0.x; acc1 = f0.y; acc2 = f1.x; acc3 = f1.y;
    }

    int e = d_off[w];
    const int eend = d_off[w + 1];
    for (; e + 4 <= eend; e += 4) {
        int s0 = __ldg(&d_csr[e]);
        int s1 = __ldg(&d_csr[e + 1]);
        int s2 = __ldg(&d_csr[e + 2]);
        int s3 = __ldg(&d_csr[e + 3]);
        uint2 ra = __ldg(gw + (size_t)s0 * 32);
        uint2 rb = __ldg(gw + (size_t)s1 * 32);
        uint2 rc = __ldg(gw + (size_t)s2 * 32);
        uint2 rd = __ldg(gw + (size_t)s3 * 32);
        float2 a0 = __half22float2(*(__half2*)&ra.x), a1 = __half22float2(*(__half2*)&ra.y);
        float2 b0 = __half22float2(*(__half2*)&rb.x), b1 = __half22float2(*(__half2*)&rb.y);
        float2 c0 = __half22float2(*(__half2*)&rc.x), c1 = __half22float2(*(__half2*)&rc.y);
        float2 d0 = __half22float2(*(__half2*)&rd.x), d1 = __half22float2(*(__half2*)&rd.y);
        acc0 += (a0.x + b0.x) + (c0.x + d0.x);
        acc1 += (a0.y + b0.y) + (c0.y + d0.y);
        acc2 += (a1.x + b1.x) + (c1.x + d1.x);
        acc3 += (a1.y + b1.y) + (c1.y + d1.y);
    }
    for (; e < eend; ++e) {
        int s0 = __ldg(&d_csr[e]);
        uint2 ra = __ldg(gw + (size_t)s0 * 32);
        float2 a0 = __half22float2(*(__half2*)&ra.x), a1 = __half22float2(*(__half2*)&ra.y);
        acc0 += a0.x; acc1 += a0.y; acc2 += a1.x; acc3 += a1.y;
    }

    const float dv = d_dinv[w];
    float4 bs = __ldg((const float4*)bias + lane);
    float r0 = dv * acc0 + bs.x;
    float r1 = dv * acc1 + bs.y;
    float r2 = dv * acc2 + bs.z;
    float r3 = dv * acc3 + bs.w;

    if (mode) {
        r0 = fmaxf(r0, 0.f); r1 = fmaxf(r1, 0.f);
        r2 = fmaxf(r2, 0.f); r3 = fmaxf(r3, 0.f);
        float f[4] = {r0, r1, r2, r3};
        alignas(8) unsigned short hb[4];
        alignas(8) unsigned short lb[4];
#pragma unroll
        for (int q = 0; q < 4; ++q) {
            __nv_bfloat16 h = __float2bfloat16_rn(f[q]);
            hb[q] = bfbits(h);
            lb[q] = bfbits(__float2bfloat16_rn(f[q] - __bfloat162float(h)));
        }
        *(uint2*)(ohi + (size_t)w * FD + lane * 4) = *(uint2*)hb;
        *(uint2*)(olo + (size_t)w * FD + lane * 4) = *(uint2*)lb;
    } else {
        ((float4*)(out + (size_t)w * FD))[lane] = make_float4(r0, r1, r2, r3);
    }
}

// ---------------------------------------------------------------------------
extern "C" void kernel_launch(void* const* d_in, const int* in_sizes, int n_in,
                              void* d_out, int out_size) {
    const float* x  = (const float*)d_in[0];
    const void*  ei = d_in[1];
    const float* W1 = (const float*)d_in[2];
    const float* b1 = (const float*)d_in[3];
    const float* W2 = (const float*)d_in[4];
    const float* b2 = (const float*)d_in[5];
    float* out = (float*)d_out;

    int n = in_sizes[0] / FD;
    if (n > NMAX) n = NMAX;
    int E = in_sizes[1] / 2;
    if (E > EMAX) E = EMAX;

    float* bufA;
    int* degi;
    unsigned short *xhi, *xlo, *hhi, *hlo, *w1hi, *w1lo, *w2hi, *w2lo;
    cudaGetSymbolAddress((void**)&bufA, d_bufA);
    cudaGetSymbolAddress((void**)&degi, d_degi);
    cudaGetSymbolAddress((void**)&xhi, d_xhi);
    cudaGetSymbolAddress((void**)&xlo, d_xlo);
    cudaGetSymbolAddress((void**)&hhi, d_hhi);
    cudaGetSymbolAddress((void**)&hlo, d_hlo);
    cudaGetSymbolAddress((void**)&w1hi, d_W1hi);
    cudaGetSymbolAddress((void**)&w1lo, d_W1lo);
    cudaGetSymbolAddress((void**)&w2hi, d_W2hi);
    cudaGetSymbolAddress((void**)&w2lo, d_W2lo);
    __half* gbuf = (__half*)bufA;

    cudaFuncSetAttribute(gemm_tc,
                         cudaFuncAttributeMaxDynamicSharedMemorySize, GEMM_SMEM);

    static cudaStream_t s_side = []() {
        cudaStream_t s;
        cudaStreamCreateWithFlags(&s, cudaStreamNonBlocking);
        return s;
    }();
    static cudaEvent_t s_fork = []() {
        cudaEvent_t e;
        cudaEventCreateWithFlags(&e, cudaEventDisableTiming);
        return e;
    }();
    static cudaEvent_t s_dinv = []() {
        cudaEvent_t e;
        cudaEventCreateWithFlags(&e, cudaEventDisableTiming);
        return e;
    }();
    static cudaEvent_t s_csr = []() {
        cudaEvent_t e;
        cudaEventCreateWithFlags(&e, cudaEventDisableTiming);
        return e;
    }();

    const int ntiles = (n + 31) / 32;
    const int ggrid = (ntiles < 2 * NSM) ? ntiles : 2 * NSM;
    const int sblk = (E + 255) / 256;

    // ---- fork: degree/dinv + CSR + W2 split on side stream ----
    cudaEventRecord(s_fork, 0);
    cudaStreamWaitEvent(s_side, s_fork, 0);
    cudaMemsetAsync(degi, 0, (size_t)n * sizeof(int), s_side);
    deg_count<<<(E + 255) / 256, 256, 0, s_side>>>(ei, E);
    scan_partial<<<SCAN_NBLK, SCAN_T, 0, s_side>>>(n);   // produces dinv
    cudaEventRecord(s_dinv, s_side);
    scan_blocksums<<<1, 32, 0, s_side>>>(SCAN_NBLK);
    scan_add<<<(n + 255) / 256, 256, 0, s_side>>>(n, E);
    scatter_ws<<<sblk + 64, 256, 0, s_side>>>(ei, E, sblk, W2);
    cudaEventRecord(s_csr, s_side);

    // ---- main: fused W1+x split; gemm1 waits only for dinv ----
    split_all<<<64 + 2 * NSM, 256>>>(x, W1, xhi, xlo, n * 16);
    cudaStreamWaitEvent(0, s_dinv, 0);
    gemm_tc<<<ggrid, 256, GEMM_SMEM>>>(xhi, xlo, w1hi, w1lo, gbuf, n, ntiles);

    // ---- join CSR; aggregate 1 (relu, h hi/lo images) ----
    cudaStreamWaitEvent(0, s_csr, 0);
    aggregate_csr<<<(n + 7) / 8, 256>>>(gbuf, b1, nullptr, hhi, hlo, n, 1);

    // ---- layer 2 ----
    gemm_tc<<<ggrid, 256, GEMM_SMEM>>>(hhi, hlo, w2hi, w2lo, gbuf, n, ntiles);
    aggregate_csr<<<(n + 7) / 8, 256>>>(gbuf, b2, out, nullptr, nullptr, n, 0);
}